// round 3
// baseline (speedup 1.0000x reference)
#include <cuda_runtime.h>
#include <math.h>

// ---------------------------------------------------------------------------
// Problem constants (fixed shapes)
// ---------------------------------------------------------------------------
#define BATCH 4
#define CIN   512
#define CC    256   // C = Cin/2
#define CQ    32    // Cq = C/8
#define NN    4096  // H*W
#define COUT  512

// Scratch layout (floats) in one big __device__ array
#define OFF_Q1  0
#define OFF_K1  (1*BATCH*CQ*NN)
#define OFF_Q2  (2*BATCH*CQ*NN)
#define OFF_K2  (3*BATCH*CQ*NN)
#define OFF_V1  (4*BATCH*CQ*NN)
#define OFF_V2  (OFF_V1 + BATCH*CC*NN)
#define OFF_CAT (OFF_V2 + BATCH*CC*NN)
#define SCRATCH_TOTAL (OFF_CAT + BATCH*CIN*NN)

__device__ __align__(16) float g_scratch[SCRATCH_TOTAL];

// ---------------------------------------------------------------------------
// Shared GEMM body: Y[o0+4ty..][n0+..] = W*X tile, 32(O) x 256(N), K=Kd.
// ---------------------------------------------------------------------------
__device__ __forceinline__
void gemm_tile_body(const float* __restrict__ W, const float* __restrict__ bias,
                    const float* __restrict__ Xb, float* __restrict__ Yb,
                    int Kd, int o0, int n0,
                    const float* __restrict__ gamma, const float* __restrict__ beta,
                    int fuse,
                    float Ws[32][32], float Xs[32][256])
{
    const int t  = threadIdx.x;
    const int tx = t & 31;
    const int ty = t >> 5;

    float acc[4][8];
#pragma unroll
    for (int i = 0; i < 4; i++)
#pragma unroll
        for (int j = 0; j < 8; j++) acc[i][j] = 0.f;

    for (int k0 = 0; k0 < Kd; k0 += 32) {
        // W tile: 32x32, 4 floats/thread
        {
            int l = t * 4;
            int r = l >> 5, c = l & 31;
            *(float4*)&Ws[r][c] = *(const float4*)(W + (long)(o0 + r) * Kd + k0 + c);
        }
        // X tile: 32x256, 8 float4/thread, fully coalesced
#pragma unroll
        for (int u = 0; u < 8; u++) {
            int f = t + 256 * u;
            int r = f >> 6;
            int c = (f & 63) * 4;
            *(float4*)&Xs[r][c] = *(const float4*)(Xb + (long)(k0 + r) * NN + n0 + c);
        }
        __syncthreads();

#pragma unroll
        for (int kk = 0; kk < 32; kk++) {
            float4 xa = *(const float4*)&Xs[kk][tx * 4];
            float4 xb = *(const float4*)&Xs[kk][tx * 4 + 128];
            float wv[4];
#pragma unroll
            for (int i = 0; i < 4; i++) wv[i] = Ws[ty * 4 + i][kk];
#pragma unroll
            for (int i = 0; i < 4; i++) {
                acc[i][0] += wv[i] * xa.x;
                acc[i][1] += wv[i] * xa.y;
                acc[i][2] += wv[i] * xa.z;
                acc[i][3] += wv[i] * xa.w;
                acc[i][4] += wv[i] * xb.x;
                acc[i][5] += wv[i] * xb.y;
                acc[i][6] += wv[i] * xb.z;
                acc[i][7] += wv[i] * xb.w;
            }
        }
        __syncthreads();
    }

    const float inv_bn = rsqrtf(1.0f + 1e-5f);
#pragma unroll
    for (int i = 0; i < 4; i++) {
        int o = o0 + ty * 4 + i;
        float bv = bias[o];
        float g = 1.f, be = 0.f;
        if (fuse) { g = gamma[o] * inv_bn; be = beta[o]; }
        float v[8];
#pragma unroll
        for (int j = 0; j < 8; j++) {
            float y = acc[i][j] + bv;
            if (fuse) {
                y = y * g + be;
                y = (y > 0.f) ? y : 0.2f * y;
            }
            v[j] = y;
        }
        float4 r0 = make_float4(v[0], v[1], v[2], v[3]);
        float4 r1 = make_float4(v[4], v[5], v[6], v[7]);
        *(float4*)(Yb + (long)o * NN + n0 + tx * 4)       = r0;
        *(float4*)(Yb + (long)o * NN + n0 + tx * 4 + 128) = r1;
    }
}

// ---------------------------------------------------------------------------
// All six projections in ONE launch. grid = (16, 20, BATCH).
//   blockIdx.y 0..3  : q1, k1, q2, k2 (Cq=32, single o-tile)
//   blockIdx.y 4..11 : v1 o-tiles 0..7
//   blockIdx.y 12..19: v2 o-tiles 0..7
// ---------------------------------------------------------------------------
__global__ __launch_bounds__(256)
void proj_kernel(const float* __restrict__ x,
                 const float* __restrict__ Wq1, const float* __restrict__ bq1,
                 const float* __restrict__ Wk1, const float* __restrict__ bk1,
                 const float* __restrict__ Wv1, const float* __restrict__ bv1,
                 const float* __restrict__ Wq2, const float* __restrict__ bq2,
                 const float* __restrict__ Wk2, const float* __restrict__ bk2,
                 const float* __restrict__ Wv2, const float* __restrict__ bv2,
                 float* __restrict__ sb)
{
    __shared__ float Ws[32][32];
    __shared__ float Xs[32][256];

    const int sy = blockIdx.y;
    const int bz = blockIdx.z;
    const int n0 = blockIdx.x * 256;
    const long XB = (long)bz * CIN * NN;

    const float *W, *bias, *Xb;
    float* Yb;
    int o0;

    if (sy < 4) {
        o0 = 0;
        switch (sy) {
            case 0:  W = Wq1; bias = bq1; Xb = x;           Yb = sb + OFF_Q1; break;
            case 1:  W = Wk1; bias = bk1; Xb = x;           Yb = sb + OFF_K1; break;
            case 2:  W = Wq2; bias = bq2; Xb = x + CC * NN; Yb = sb + OFF_Q2; break;
            default: W = Wk2; bias = bk2; Xb = x + CC * NN; Yb = sb + OFF_K2; break;
        }
        Xb += XB;
        Yb += (long)bz * CQ * NN;
    } else {
        int v  = sy - 4;
        int br = v >> 3;
        o0 = (v & 7) * 32;
        W    = br ? Wv2 : Wv1;
        bias = br ? bv2 : bv1;
        Xb   = x + (long)br * CC * NN + XB;
        Yb   = sb + (br ? OFF_V2 : OFF_V1) + (long)bz * CC * NN;
    }

    gemm_tile_body(W, bias, Xb, Yb, CC, o0, n0, nullptr, nullptr, 0, Ws, Xs);
}

// ---------------------------------------------------------------------------
// Final 1x1 conv (K=512) + BN(eval) + LeakyReLU fused
// ---------------------------------------------------------------------------
__global__ __launch_bounds__(256)
void outconv_kernel(const float* __restrict__ W, const float* __restrict__ bias,
                    const float* __restrict__ X, float* __restrict__ Y,
                    const float* __restrict__ gamma, const float* __restrict__ beta)
{
    __shared__ float Ws[32][32];
    __shared__ float Xs[32][256];

    const int n0 = blockIdx.x * 256;
    const int o0 = blockIdx.y * 32;
    const float* Xb = X + (long)blockIdx.z * CIN * NN;
    float*       Yb = Y + (long)blockIdx.z * COUT * NN;

    gemm_tile_body(W, bias, Xb, Yb, CIN, o0, n0, gamma, beta, 1, Ws, Xs);
}

// ---------------------------------------------------------------------------
// Fused flash cross-attention (fp32, non-causal, no logit scale)
//   logits[n][m] = sum_d Q[d][n]*K[d][m]; softmax over m;
//   out[c][n]    = sum_m V[c][m]*P[n][m]
// Per block: 64 queries. Streams 64-key tiles. d=32, Cv=256.
// Block 256 threads, O accumulator 64x256 fp32 in registers (8q x 8c /thread).
// ---------------------------------------------------------------------------
struct __align__(16) AttnSmem {
    float Qs[32][64];     //  8 KB   Q[d][i]
    float Ks[32][64];     //  8 KB   K[d][j]
    float Vs[256][68];    // 68 KB   V[c][j] (pitch 68 -> conflict-free f4)
    float Ps[64][68];     // 17 KB   P[i][j] (pitch 68)
    float red[64][4];     // partial max/sum per (row, jgroup)
    float m_run[64];
    float l_run[64];
    float alpha_s[64];
};

extern __shared__ char attn_smem_raw[];

__global__ __launch_bounds__(256)
void flash_attn_kernel()
{
    AttnSmem& sm = *reinterpret_cast<AttnSmem*>(attn_smem_raw);

    const int t    = threadIdx.x;
    const int lane = t & 31;
    const int warp = t >> 5;
    const int n0   = blockIdx.x * 64;   // query tile
    const int a    = blockIdx.y;        // which cross-attention
    const int b    = blockIdx.z;        // batch

    const float* Q = g_scratch + (a == 0 ? OFF_Q2 : OFF_Q1) + (long)b * CQ * NN;
    const float* K = g_scratch + (a == 0 ? OFF_K1 : OFF_K2) + (long)b * CQ * NN;
    const float* V = g_scratch + (a == 0 ? OFF_V1 : OFF_V2) + (long)b * CC * NN;
    float*     Out = g_scratch + OFF_CAT + (long)b * CIN * NN + (long)a * CC * NN;

    // Load Q tile [32][64]: 8 floats/thread
    {
        int l = t * 8;
        int d = l >> 6, i = l & 63;
        const float4* src = (const float4*)(Q + (long)d * NN + n0 + i);
        float4* dst = (float4*)&sm.Qs[d][i];
        dst[0] = src[0];
        dst[1] = src[1];
    }
    if (t < 64) { sm.m_run[t] = -3.0e38f; sm.l_run[t] = 0.f; }

    float acc[8][8];
#pragma unroll
    for (int qi = 0; qi < 8; qi++)
#pragma unroll
        for (int cc = 0; cc < 8; cc++) acc[qi][cc] = 0.f;

    const int si  = t & 63;       // S-stage: row i
    const int sjg = t >> 6;       // S-stage: j-group (16 keys)
    const int sjb = sjg * 16;
    const int q0  = warp * 8;     // PV-stage: query base

    for (int kt = 0; kt < 64; kt++) {
        const int m0 = kt * 64;

        // Load K tile [32][64]
        {
            int l = t * 8;
            int d = l >> 6, j = l & 63;
            const float4* src = (const float4*)(K + (long)d * NN + m0 + j);
            float4* dst = (float4*)&sm.Ks[d][j];
            dst[0] = src[0];
            dst[1] = src[1];
        }
        // Load V tile [256 c][64 j]: 16 float4/thread, coalesced along j
        {
            int j4 = t & 15;
            int cbase = t >> 4;
#pragma unroll
            for (int r = 0; r < 16; r++) {
                int c = cbase + 16 * r;
                *(float4*)&sm.Vs[c][j4 * 4] =
                    *(const float4*)(V + (long)c * NN + m0 + j4 * 4);
            }
        }
        __syncthreads();   // (A) tiles visible

        // --- S = Q^T K : each thread 1 row x 16 cols ---
        float s[16];
#pragma unroll
        for (int x = 0; x < 16; x++) s[x] = 0.f;
#pragma unroll
        for (int d = 0; d < 32; d++) {
            float qv = sm.Qs[d][si];
#pragma unroll
            for (int x = 0; x < 4; x++) {
                float4 kv = *(const float4*)&sm.Ks[d][sjb + 4 * x];
                s[4 * x + 0] += qv * kv.x;
                s[4 * x + 1] += qv * kv.y;
                s[4 * x + 2] += qv * kv.z;
                s[4 * x + 3] += qv * kv.w;
            }
        }
        float tmax = s[0];
#pragma unroll
        for (int x = 1; x < 16; x++) tmax = fmaxf(tmax, s[x]);
        sm.red[si][sjg] = tmax;
        __syncthreads();   // (B) partial maxes visible

        if (t < 64) {
            float m_old = sm.m_run[t];
            float tm = fmaxf(fmaxf(sm.red[t][0], sm.red[t][1]),
                             fmaxf(sm.red[t][2], sm.red[t][3]));
            float m_new = fmaxf(m_old, tm);
            float al = __expf(m_old - m_new);
            sm.alpha_s[t] = al;
            sm.m_run[t]   = m_new;
            sm.l_run[t]  *= al;
        }
        __syncthreads();   // (C) m_new / alpha visible

        // --- P = exp(S - m), write to smem, partial row-sums ---
        {
            float mrow = sm.m_run[si];
            float lsum = 0.f;
#pragma unroll
            for (int x = 0; x < 4; x++) {
                float4 p;
                p.x = __expf(s[4 * x + 0] - mrow);
                p.y = __expf(s[4 * x + 1] - mrow);
                p.z = __expf(s[4 * x + 2] - mrow);
                p.w = __expf(s[4 * x + 3] - mrow);
                lsum += p.x + p.y + p.z + p.w;
                *(float4*)&sm.Ps[si][sjb + 4 * x] = p;
            }
            sm.red[si][sjg] = lsum;
        }

        // Rescale accumulators by alpha (stable since barrier C)
        {
            float alq[8];
#pragma unroll
            for (int qi = 0; qi < 8; qi++) alq[qi] = sm.alpha_s[q0 + qi];
#pragma unroll
            for (int qi = 0; qi < 8; qi++)
#pragma unroll
                for (int cc = 0; cc < 8; cc++) acc[qi][cc] *= alq[qi];
        }
        __syncthreads();   // (D) P + partial sums visible

        if (t < 64)
            sm.l_run[t] += sm.red[t][0] + sm.red[t][1] + sm.red[t][2] + sm.red[t][3];

        // --- O += P * V^T : 8 queries x 8 channels per thread ---
#pragma unroll 2
        for (int j4 = 0; j4 < 16; j4++) {
            float4 v4[8];
#pragma unroll
            for (int cc = 0; cc < 8; cc++)
                v4[cc] = *(const float4*)&sm.Vs[lane + 32 * cc][4 * j4];
#pragma unroll
            for (int qi = 0; qi < 8; qi++) {
                float4 p = *(const float4*)&sm.Ps[q0 + qi][4 * j4];
#pragma unroll
                for (int cc = 0; cc < 8; cc++) {
                    acc[qi][cc] += p.x * v4[cc].x;
                    acc[qi][cc] += p.y * v4[cc].y;
                    acc[qi][cc] += p.z * v4[cc].z;
                    acc[qi][cc] += p.w * v4[cc].w;
                }
            }
        }
        __syncthreads();   // (E) safe to overwrite tiles next iter
    }

    // --- Normalize, stage through smem for coalesced [c][n] output ---
    float* stage = (float*)sm.Vs;   // 64 x pitch-257 fits in Vs
    {
        float linv[8];
#pragma unroll
        for (int qi = 0; qi < 8; qi++) linv[qi] = 1.0f / sm.l_run[q0 + qi];
#pragma unroll
        for (int qi = 0; qi < 8; qi++)
#pragma unroll
            for (int cc = 0; cc < 8; cc++)
                stage[(q0 + qi) * 257 + lane + 32 * cc] = acc[qi][cc] * linv[qi];
    }
    __syncthreads();
    {
        int qb = (t & 15) * 4;
        int cb = t >> 4;
#pragma unroll
        for (int r = 0; r < 16; r++) {
            int c = cb + 16 * r;
            float4 o;
            o.x = stage[(qb + 0) * 257 + c];
            o.y = stage[(qb + 1) * 257 + c];
            o.z = stage[(qb + 2) * 257 + c];
            o.w = stage[(qb + 3) * 257 + c];
            *(float4*)(Out + (long)c * NN + n0 + qb) = o;
        }
    }
}

// ---------------------------------------------------------------------------
// Launch
// ---------------------------------------------------------------------------
extern "C" void kernel_launch(void* const* d_in, const int* in_sizes, int n_in,
                              void* d_out, int out_size)
{
    const float* x   = (const float*)d_in[0];
    const float* Wq1 = (const float*)d_in[1];
    const float* bq1 = (const float*)d_in[2];
    const float* Wk1 = (const float*)d_in[3];
    const float* bk1 = (const float*)d_in[4];
    const float* Wv1 = (const float*)d_in[5];
    const float* bv1 = (const float*)d_in[6];
    const float* Wq2 = (const float*)d_in[7];
    const float* bq2 = (const float*)d_in[8];
    const float* Wk2 = (const float*)d_in[9];
    const float* bk2 = (const float*)d_in[10];
    const float* Wv2 = (const float*)d_in[11];
    const float* bv2 = (const float*)d_in[12];
    const float* Wc  = (const float*)d_in[13];
    const float* bc  = (const float*)d_in[14];
    const float* gam = (const float*)d_in[15];
    const float* bet = (const float*)d_in[16];
    float* out = (float*)d_out;

    float* sb = nullptr;
    cudaGetSymbolAddress((void**)&sb, g_scratch);

    const dim3 blk(256);

    // All six projections in one launch
    proj_kernel<<<dim3(16, 20, BATCH), blk>>>(x,
        Wq1, bq1, Wk1, bk1, Wv1, bv1,
        Wq2, bq2, Wk2, bk2, Wv2, bv2, sb);

    // Fused dual cross-attention
    const int attn_smem = (int)sizeof(AttnSmem);
    cudaFuncSetAttribute(flash_attn_kernel,
                         cudaFuncAttributeMaxDynamicSharedMemorySize, attn_smem);
    flash_attn_kernel<<<dim3(NN / 64, 2, BATCH), blk, attn_smem>>>();

    // Final 1x1 conv + BN(eval) + LeakyReLU fused
    outconv_kernel<<<dim3(16, 16, BATCH), blk>>>(Wc, bc, sb + OFF_CAT, out, gam, bet);
}